// round 12
// baseline (speedup 1.0000x reference)
#include <cuda_runtime.h>
#include <cuda_bf16.h>
#include <cstdint>

// Problem constants
constexpr int NB  = 2;    // batch
constexpr int NN  = 768;  // nodes
constexpr int NU  = 64;   // embed dim
constexpr int NK  = 8;    // relation dim
constexpr int NIN = 136;  // 2U + K
constexpr int NPD = 160;  // padded hidden (5 per lane * 32 lanes)
constexpr float SLOPE = 0.01f;

// precompute tiling (R7 proven shape)
constexpr int RPB = 4;
constexpr int KH  = 2;
constexpr int PTHREADS = NPD * KH;  // 320

// ---------------- device scratch ----------------
__device__ unsigned char g_mask[NN * NN];
__device__ float g_invD[NN];
__device__ int   g_colcnt[NN];
__device__ int   g_colrows[NN * NN];   // per-column row lists (i-ordered)
__device__ float g_A   [NB * NN * NPD];
__device__ float g_Base[NB * NN * NPD];
__device__ float g_x1  [NB * NN * NU];

// ---------------- kernel 1: mask + row degree + invD ----------------
__global__ void maskdeg_kernel(const float* __restrict__ rel) {
    int i = blockIdx.x;
    int tid = threadIdx.x;
    int cnt = 0;
    for (int j = tid; j < NN; j += 256) {
        const float4* p = reinterpret_cast<const float4*>(rel + ((size_t)i * NN + j) * NK);
        float4 a = p[0], b = p[1];
        float s = a.x + a.y + a.z + a.w + b.x + b.y + b.z + b.w;
        unsigned char m = (s > 0.0f) ? 1 : 0;
        g_mask[i * NN + j] = m;
        cnt += m;
    }
    #pragma unroll
    for (int o = 16; o > 0; o >>= 1) cnt += __shfl_xor_sync(~0u, cnt, o);
    __shared__ int wsum[8];
    if ((tid & 31) == 0) wsum[tid >> 5] = cnt;
    __syncthreads();
    if (tid == 0) {
        int t = 0;
        #pragma unroll
        for (int w = 0; w < 8; w++) t += wsum[w];
        g_invD[i] = 1.0f / (float)(t > 0 ? t : 1);
    }
}

// ---------------- kernel 2: per-column lists + counts (ballot compaction) ----------------
__global__ void colbuild_kernel() {
    int j = blockIdx.x;
    int tid = threadIdx.x;          // row i
    int warp = tid >> 5, lane = tid & 31;
    int flag = g_mask[tid * NN + j];
    unsigned bal = __ballot_sync(~0u, flag != 0);
    __shared__ int wcnt[24];
    __shared__ int wpre[25];
    if (lane == 0) wcnt[warp] = __popc(bal);
    __syncthreads();
    if (tid == 0) {
        int acc = 0;
        #pragma unroll
        for (int w = 0; w < 24; w++) { wpre[w] = acc; acc += wcnt[w]; }
        wpre[24] = acc;
        g_colcnt[j] = acc;
    }
    __syncthreads();
    if (flag) {
        int pos = wpre[warp] + __popc(bal & ((1u << lane) - 1u));
        g_colrows[j * NN + pos] = tid;
    }
}

// ---------------- precompute GEMM (R7 proven: KH=2, 320 threads, RPB=4) ----------------
__global__ void __launch_bounds__(PTHREADS) precompute_kernel(
    const float* __restrict__ xext, int use_g,
    const float* __restrict__ W1,
    const float* __restrict__ b1) {
    const float* xp = use_g ? g_x1 : xext;
    __shared__ float sx[RPB][NU];
    __shared__ float spA[RPB][NPD];
    __shared__ float spB[RPB][NPD];
    int R0 = blockIdx.x * RPB;
    int tid = threadIdx.x;
    for (int idx = tid; idx < RPB * NU; idx += PTHREADS)
        sx[idx >> 6][idx & 63] = xp[(size_t)R0 * NU + idx];
    __syncthreads();

    int n  = tid % NPD;
    int kh = tid / NPD;
    float a[RPB], bs[RPB];
    #pragma unroll
    for (int r = 0; r < RPB; r++) { a[r] = 0.0f; bs[r] = 0.0f; }
    if (n < NIN) {
        int ub = kh * 32;
        #pragma unroll 4
        for (int u0 = 0; u0 < 32; u0++) {
            int u = ub + u0;
            float wa = W1[u * NIN + n];
            float wb = W1[(NU + u) * NIN + n];
            #pragma unroll
            for (int r = 0; r < RPB; r++) {
                a[r]  = fmaf(sx[r][u], wa, a[r]);
                bs[r] = fmaf(sx[r][u], wb, bs[r]);
            }
        }
    }
    if (kh == 1) {
        #pragma unroll
        for (int r = 0; r < RPB; r++) { spA[r][n] = a[r]; spB[r][n] = bs[r]; }
    }
    __syncthreads();
    if (kh == 0) {
        float bb = (n < NIN) ? b1[n] : 0.0f;
        #pragma unroll
        for (int r = 0; r < RPB; r++) {
            g_A   [(size_t)(R0 + r) * NPD + n] = a[r] + spA[r][n];
            g_Base[(size_t)(R0 + r) * NPD + n] = bs[r] + spB[r][n] + bb;
        }
    }
}

// ---------------- kernel 4: edge phase ----------------
// Block = 2 columns x 4 subsets (8 warps). Warp (jc, sub) processes 2 edges x
// 2 batches per iteration; the rel-term MLP contribution is computed ONCE per
// edge (batch-independent) and shared by both batch chains.
__global__ void __launch_bounds__(256, 4) edge_kernel(
    const float* __restrict__ xin_ext, float* __restrict__ xout_ext,
    int use_g_in, int use_g_out,
    const float* __restrict__ rel,
    const float* __restrict__ W1,      // rows 128..135 = rel weights
    const float* __restrict__ w2,
    const float* __restrict__ b2p)
{
    const float* xin  = use_g_in  ? g_x1 : xin_ext;
    float*       xout = use_g_out ? g_x1 : xout_ext;

    __shared__ float sW1c[NK * NPD];
    __shared__ float sacc[2][4][2];    // [jc][sub][batch]

    int tid = threadIdx.x, warp = tid >> 5, lane = tid & 31;

    for (int idx = tid; idx < NK * NPD; idx += 256) {
        int kk = idx / NPD, n = idx % NPD;
        sW1c[idx] = (n < NIN) ? W1[(2 * NU + kk) * NIN + n] : 0.0f;
    }
    float w2l[5];
    #pragma unroll
    for (int m = 0; m < 5; m++) {
        int n = lane + 32 * m;
        w2l[m] = (n < NIN) ? w2[n] : 0.0f;
    }
    float b2 = __ldg(b2p);
    __syncthreads();

    int jc  = warp >> 2;               // 0..1
    int sub = warp & 3;                // 0..3
    int j   = blockIdx.x * 2 + jc;
    int cnt = g_colcnt[j];
    const int* rows = g_colrows + j * NN;

    // hoist Base for (b=0,j) and (b=1,j)
    float base[2][5];
    #pragma unroll
    for (int b = 0; b < 2; b++) {
        const float* Bs = g_Base + ((size_t)(b * NN + j)) * NPD;
        #pragma unroll
        for (int m = 0; m < 5; m++) base[b][m] = Bs[lane + 32 * m];
    }

    float wacc[2] = {0.0f, 0.0f};
    for (int g = sub; 2 * g < cnt; g += 4) {
        int e0 = 2 * g;
        float vdv[2];
        float rv[2][8];
        float av[4][5];     // A loads, chain c = s*2 + b
        int iv[2];

        // front-batched loads: rel (2x LDG.128) + invD + A rows (20x LDG.32)
        #pragma unroll
        for (int s = 0; s < 2; s++) {
            int e = e0 + s;
            bool v = (e < cnt);
            int i = rows[v ? e : 0];
            iv[s] = i;
            vdv[s] = v ? g_invD[i] : 0.0f;
            const float4* rp = reinterpret_cast<const float4*>(
                rel + ((size_t)i * NN + j) * NK);
            float4 r0 = rp[0], r1 = rp[1];
            rv[s][0] = r0.x; rv[s][1] = r0.y; rv[s][2] = r0.z; rv[s][3] = r0.w;
            rv[s][4] = r1.x; rv[s][5] = r1.y; rv[s][6] = r1.z; rv[s][7] = r1.w;
        }
        #pragma unroll
        for (int s = 0; s < 2; s++)
            #pragma unroll
            for (int b = 0; b < 2; b++) {
                const float* Ar = g_A + ((size_t)(b * NN + iv[s])) * NPD;
                #pragma unroll
                for (int m = 0; m < 5; m++)
                    av[s * 2 + b][m] = Ar[lane + 32 * m];
            }

        // rel-term once per EDGE (batch-independent): relc[s][m]
        float relc[2][5];
        #pragma unroll
        for (int s = 0; s < 2; s++)
            #pragma unroll
            for (int m = 0; m < 5; m++) relc[s][m] = 0.0f;
        #pragma unroll
        for (int kk = 0; kk < NK; kk++) {
            float w1v[5];
            #pragma unroll
            for (int m = 0; m < 5; m++)
                w1v[m] = sW1c[kk * NPD + lane + 32 * m];
            #pragma unroll
            for (int s = 0; s < 2; s++)
                #pragma unroll
                for (int m = 0; m < 5; m++)
                    relc[s][m] = fmaf(rv[s][kk], w1v[m], relc[s][m]);
        }

        // per chain: h = A + base + relc, leaky, dot w2
        float d[4];
        #pragma unroll
        for (int c = 0; c < 4; c++) {
            int s = c >> 1, b = c & 1;
            float acc = 0.0f;
            #pragma unroll
            for (int m = 0; m < 5; m++) {
                float hv = av[c][m] + (base[b][m] + relc[s][m]);
                hv = fmaxf(hv, SLOPE * hv);
                acc = fmaf(hv, w2l[m], acc);
            }
            d[c] = acc;
        }
        #pragma unroll
        for (int o = 16; o > 0; o >>= 1) {
            #pragma unroll
            for (int c = 0; c < 4; c++)
                d[c] += __shfl_xor_sync(~0u, d[c], o);
        }
        #pragma unroll
        for (int c = 0; c < 4; c++) {
            int s = c >> 1, b = c & 1;
            float o2 = d[c] + b2;
            o2 = fmaxf(o2, SLOPE * o2);
            wacc[b] = fmaf(o2, vdv[s], wacc[b]);
        }
    }

    if (lane == 0) {
        sacc[jc][sub][0] = wacc[0];
        sacc[jc][sub][1] = wacc[1];
    }
    __syncthreads();

    // warps 0..3 write outputs: warp w -> (jc2 = w>>1, b = w&1)
    if (warp < 4) {
        int jc2 = warp >> 1, b = warp & 1;
        int j2 = blockIdx.x * 2 + jc2;
        float S = ((sacc[jc2][0][b] + sacc[jc2][1][b])
                 +  sacc[jc2][2][b]) + sacc[jc2][3][b];
        size_t obase = ((size_t)(b * NN + j2)) * NU;
        xout[obase + lane]      = xin[obase + lane]      * S;
        xout[obase + 32 + lane] = xin[obase + 32 + lane] * S;
    }
}

// ---------------- launch ----------------
extern "C" void kernel_launch(void* const* d_in, const int* in_sizes, int n_in,
                              void* d_out, int out_size) {
    const float* seq  = (const float*)d_in[0];
    const float* rel  = (const float*)d_in[1];
    const float* w1_1 = (const float*)d_in[2];
    const float* b1_1 = (const float*)d_in[3];
    const float* w1_2 = (const float*)d_in[4];
    const float* b1_2 = (const float*)d_in[5];
    const float* w2_1 = (const float*)d_in[6];
    const float* b2_1 = (const float*)d_in[7];
    const float* w2_2 = (const float*)d_in[8];
    const float* b2_2 = (const float*)d_in[9];
    float* out = (float*)d_out;

    maskdeg_kernel <<<NN, 256>>>(rel);
    colbuild_kernel<<<NN, 768>>>();

    const int PGRID = NB * NN / RPB;   // 384
    const int EGRID = NN / 2;          // 384

    // hop 1: seq -> g_x1 (edge kernel writes x1 directly)
    precompute_kernel<<<PGRID, PTHREADS>>>(seq, 0, w1_1, b1_1);
    edge_kernel      <<<EGRID, 256>>>(seq, nullptr, 0, 1, rel, w1_1, w1_2, b1_2);

    // hop 2: g_x1 -> out
    precompute_kernel<<<PGRID, PTHREADS>>>(nullptr, 1, w2_1, b2_1);
    edge_kernel      <<<EGRID, 256>>>(nullptr, out, 1, 0, rel, w2_1, w2_2, b2_2);
}

// round 13
// speedup vs baseline: 1.2717x; 1.2717x over previous
#include <cuda_runtime.h>
#include <cuda_bf16.h>
#include <cstdint>

// Problem constants
constexpr int NB  = 2;    // batch
constexpr int NN  = 768;  // nodes
constexpr int NU  = 64;   // embed dim
constexpr int NK  = 8;    // relation dim
constexpr int NIN = 136;  // 2U + K
constexpr int NPD = 160;  // padded hidden (5 per lane * 32 lanes)
constexpr float SLOPE = 0.01f;

// precompute tiling (R7 proven shape)
constexpr int RPB = 4;
constexpr int KH  = 2;
constexpr int PTHREADS = NPD * KH;  // 320

// ---------------- device scratch ----------------
__device__ unsigned char g_mask[NN * NN];
__device__ float g_invD[NN];
__device__ int   g_colcnt[NN];
__device__ int   g_colrows[NN * NN];   // per-column row lists (i-ordered)
__device__ float g_A   [NB * NN * NPD];
__device__ float g_Base[NB * NN * NPD];
__device__ float g_x1  [NB * NN * NU];

// ---------------- kernel 1: mask + row degree + invD ----------------
__global__ void maskdeg_kernel(const float* __restrict__ rel) {
    int i = blockIdx.x;
    int tid = threadIdx.x;
    int cnt = 0;
    for (int j = tid; j < NN; j += 256) {
        const float4* p = reinterpret_cast<const float4*>(rel + ((size_t)i * NN + j) * NK);
        float4 a = p[0], b = p[1];
        float s = a.x + a.y + a.z + a.w + b.x + b.y + b.z + b.w;
        unsigned char m = (s > 0.0f) ? 1 : 0;
        g_mask[i * NN + j] = m;
        cnt += m;
    }
    #pragma unroll
    for (int o = 16; o > 0; o >>= 1) cnt += __shfl_xor_sync(~0u, cnt, o);
    __shared__ int wsum[8];
    if ((tid & 31) == 0) wsum[tid >> 5] = cnt;
    __syncthreads();
    if (tid == 0) {
        int t = 0;
        #pragma unroll
        for (int w = 0; w < 8; w++) t += wsum[w];
        g_invD[i] = 1.0f / (float)(t > 0 ? t : 1);
    }
}

// ---------------- kernel 2: per-column lists + counts (ballot compaction) ----------------
__global__ void colbuild_kernel() {
    int j = blockIdx.x;
    int tid = threadIdx.x;          // row i
    int warp = tid >> 5, lane = tid & 31;
    int flag = g_mask[tid * NN + j];
    unsigned bal = __ballot_sync(~0u, flag != 0);
    __shared__ int wcnt[24];
    __shared__ int wpre[25];
    if (lane == 0) wcnt[warp] = __popc(bal);
    __syncthreads();
    if (tid == 0) {
        int acc = 0;
        #pragma unroll
        for (int w = 0; w < 24; w++) { wpre[w] = acc; acc += wcnt[w]; }
        wpre[24] = acc;
        g_colcnt[j] = acc;
    }
    __syncthreads();
    if (flag) {
        int pos = wpre[warp] + __popc(bal & ((1u << lane) - 1u));
        g_colrows[j * NN + pos] = tid;
    }
}

// ---------------- precompute GEMM (R7 proven: KH=2, 320 threads, RPB=4) ----------------
__global__ void __launch_bounds__(PTHREADS) precompute_kernel(
    const float* __restrict__ xext, int use_g,
    const float* __restrict__ W1,
    const float* __restrict__ b1) {
    const float* xp = use_g ? g_x1 : xext;
    __shared__ float sx[RPB][NU];
    __shared__ float spA[RPB][NPD];
    __shared__ float spB[RPB][NPD];
    int R0 = blockIdx.x * RPB;
    int tid = threadIdx.x;
    for (int idx = tid; idx < RPB * NU; idx += PTHREADS)
        sx[idx >> 6][idx & 63] = xp[(size_t)R0 * NU + idx];
    __syncthreads();

    int n  = tid % NPD;
    int kh = tid / NPD;
    float a[RPB], bs[RPB];
    #pragma unroll
    for (int r = 0; r < RPB; r++) { a[r] = 0.0f; bs[r] = 0.0f; }
    if (n < NIN) {
        int ub = kh * 32;
        #pragma unroll 4
        for (int u0 = 0; u0 < 32; u0++) {
            int u = ub + u0;
            float wa = W1[u * NIN + n];
            float wb = W1[(NU + u) * NIN + n];
            #pragma unroll
            for (int r = 0; r < RPB; r++) {
                a[r]  = fmaf(sx[r][u], wa, a[r]);
                bs[r] = fmaf(sx[r][u], wb, bs[r]);
            }
        }
    }
    if (kh == 1) {
        #pragma unroll
        for (int r = 0; r < RPB; r++) { spA[r][n] = a[r]; spB[r][n] = bs[r]; }
    }
    __syncthreads();
    if (kh == 0) {
        float bb = (n < NIN) ? b1[n] : 0.0f;
        #pragma unroll
        for (int r = 0; r < RPB; r++) {
            g_A   [(size_t)(R0 + r) * NPD + n] = a[r] + spA[r][n];
            g_Base[(size_t)(R0 + r) * NPD + n] = bs[r] + spB[r][n] + bb;
        }
    }
}

// ---------------- kernel 4: edge phase ----------------
// Block = 2 columns x 4 subsets (8 warps). Warp (jc, sub) processes 2 edges x
// 2 batches per iteration; rel-term computed once per edge, shared by batches.
// launch_bounds(256,3): keep register headroom for the front-batched loads.
__global__ void __launch_bounds__(256, 3) edge_kernel(
    const float* __restrict__ xin_ext, float* __restrict__ xout_ext,
    int use_g_in, int use_g_out,
    const float* __restrict__ rel,
    const float* __restrict__ W1,      // rows 128..135 = rel weights
    const float* __restrict__ w2,
    const float* __restrict__ b2p)
{
    const float* xin  = use_g_in  ? g_x1 : xin_ext;
    float*       xout = use_g_out ? g_x1 : xout_ext;

    __shared__ float sW1c[NK * NPD];
    __shared__ float sacc[2][4][2];    // [jc][sub][batch]

    int tid = threadIdx.x, warp = tid >> 5, lane = tid & 31;

    for (int idx = tid; idx < NK * NPD; idx += 256) {
        int kk = idx / NPD, n = idx % NPD;
        sW1c[idx] = (n < NIN) ? W1[(2 * NU + kk) * NIN + n] : 0.0f;
    }
    float w2l[5];
    #pragma unroll
    for (int m = 0; m < 5; m++) {
        int n = lane + 32 * m;
        w2l[m] = (n < NIN) ? w2[n] : 0.0f;
    }
    float b2 = __ldg(b2p);
    __syncthreads();

    int jc  = warp >> 2;               // 0..1
    int sub = warp & 3;                // 0..3
    int j   = blockIdx.x * 2 + jc;
    int cnt = g_colcnt[j];
    const int* rows = g_colrows + j * NN;

    // hoist Base for (b=0,j) and (b=1,j)
    float base[2][5];
    #pragma unroll
    for (int b = 0; b < 2; b++) {
        const float* Bs = g_Base + ((size_t)(b * NN + j)) * NPD;
        #pragma unroll
        for (int m = 0; m < 5; m++) base[b][m] = Bs[lane + 32 * m];
    }

    float wacc[2] = {0.0f, 0.0f};
    for (int g = sub; 2 * g < cnt; g += 4) {
        int e0 = 2 * g;
        float vdv[2];
        float rv[2][8];
        float av[4][5];     // A loads, chain c = s*2 + b
        int iv[2];

        // front-batched loads: 2x rel LDG.128 + 2x invD + 20x A LDG.32
        #pragma unroll
        for (int s = 0; s < 2; s++) {
            int e = e0 + s;
            bool v = (e < cnt);
            int i = rows[v ? e : 0];
            iv[s] = i;
            vdv[s] = v ? g_invD[i] : 0.0f;
            const float4* rp = reinterpret_cast<const float4*>(
                rel + ((size_t)i * NN + j) * NK);
            float4 r0 = rp[0], r1 = rp[1];
            rv[s][0] = r0.x; rv[s][1] = r0.y; rv[s][2] = r0.z; rv[s][3] = r0.w;
            rv[s][4] = r1.x; rv[s][5] = r1.y; rv[s][6] = r1.z; rv[s][7] = r1.w;
        }
        #pragma unroll
        for (int s = 0; s < 2; s++)
            #pragma unroll
            for (int b = 0; b < 2; b++) {
                const float* Ar = g_A + ((size_t)(b * NN + iv[s])) * NPD;
                #pragma unroll
                for (int m = 0; m < 5; m++)
                    av[s * 2 + b][m] = Ar[lane + 32 * m];
            }

        // rel-term once per EDGE (batch-independent)
        float relc[2][5];
        #pragma unroll
        for (int s = 0; s < 2; s++)
            #pragma unroll
            for (int m = 0; m < 5; m++) relc[s][m] = 0.0f;
        #pragma unroll
        for (int kk = 0; kk < NK; kk++) {
            float w1v[5];
            #pragma unroll
            for (int m = 0; m < 5; m++)
                w1v[m] = sW1c[kk * NPD + lane + 32 * m];
            #pragma unroll
            for (int s = 0; s < 2; s++)
                #pragma unroll
                for (int m = 0; m < 5; m++)
                    relc[s][m] = fmaf(rv[s][kk], w1v[m], relc[s][m]);
        }
        // fold base into relc per (s,b) once (CSE across the two uses below)
        float d[4];
        #pragma unroll
        for (int c = 0; c < 4; c++) {
            int s = c >> 1, b = c & 1;
            float acc = 0.0f;
            #pragma unroll
            for (int m = 0; m < 5; m++) {
                float hv = av[c][m] + (base[b][m] + relc[s][m]);
                hv = fmaxf(hv, SLOPE * hv);
                acc = fmaf(hv, w2l[m], acc);
            }
            d[c] = acc;
        }
        #pragma unroll
        for (int o = 16; o > 0; o >>= 1) {
            #pragma unroll
            for (int c = 0; c < 4; c++)
                d[c] += __shfl_xor_sync(~0u, d[c], o);
        }
        #pragma unroll
        for (int c = 0; c < 4; c++) {
            int s = c >> 1, b = c & 1;
            float o2 = d[c] + b2;
            o2 = fmaxf(o2, SLOPE * o2);
            wacc[b] = fmaf(o2, vdv[s], wacc[b]);
        }
    }

    if (lane == 0) {
        sacc[jc][sub][0] = wacc[0];
        sacc[jc][sub][1] = wacc[1];
    }
    __syncthreads();

    // warps 0..3 write outputs: warp w -> (jc2 = w>>1, b = w&1)
    if (warp < 4) {
        int jc2 = warp >> 1, b = warp & 1;
        int j2 = blockIdx.x * 2 + jc2;
        float S = ((sacc[jc2][0][b] + sacc[jc2][1][b])
                 +  sacc[jc2][2][b]) + sacc[jc2][3][b];
        size_t obase = ((size_t)(b * NN + j2)) * NU;
        xout[obase + lane]      = xin[obase + lane]      * S;
        xout[obase + 32 + lane] = xin[obase + 32 + lane] * S;
    }
}

// ---------------- launch ----------------
extern "C" void kernel_launch(void* const* d_in, const int* in_sizes, int n_in,
                              void* d_out, int out_size) {
    const float* seq  = (const float*)d_in[0];
    const float* rel  = (const float*)d_in[1];
    const float* w1_1 = (const float*)d_in[2];
    const float* b1_1 = (const float*)d_in[3];
    const float* w1_2 = (const float*)d_in[4];
    const float* b1_2 = (const float*)d_in[5];
    const float* w2_1 = (const float*)d_in[6];
    const float* b2_1 = (const float*)d_in[7];
    const float* w2_2 = (const float*)d_in[8];
    const float* b2_2 = (const float*)d_in[9];
    float* out = (float*)d_out;

    maskdeg_kernel <<<NN, 256>>>(rel);
    colbuild_kernel<<<NN, 768>>>();

    const int PGRID = NB * NN / RPB;   // 384
    const int EGRID = NN / 2;          // 384

    // hop 1: seq -> g_x1 (edge kernel writes x1 directly)
    precompute_kernel<<<PGRID, PTHREADS>>>(seq, 0, w1_1, b1_1);
    edge_kernel      <<<EGRID, 256>>>(seq, nullptr, 0, 1, rel, w1_1, w1_2, b1_2);

    // hop 2: g_x1 -> out
    precompute_kernel<<<PGRID, PTHREADS>>>(nullptr, 1, w2_1, b2_1);
    edge_kernel      <<<EGRID, 256>>>(nullptr, out, 1, 0, rel, w2_1, w2_2, b2_2);
}

// round 14
// speedup vs baseline: 1.2725x; 1.0006x over previous
#include <cuda_runtime.h>
#include <cuda_bf16.h>
#include <cstdint>

// Problem constants
constexpr int NB  = 2;    // batch
constexpr int NN  = 768;  // nodes
constexpr int NU  = 64;   // embed dim
constexpr int NK  = 8;    // relation dim
constexpr int NIN = 136;  // 2U + K
constexpr int NPD = 160;  // padded hidden (5 per lane * 32 lanes)
constexpr float SLOPE = 0.01f;

// precompute tiling (R7 proven shape)
constexpr int RPB = 4;
constexpr int KH  = 2;
constexpr int PTHREADS = NPD * KH;  // 320

// ---------------- device scratch ----------------
__device__ unsigned char g_mask[NN * NN];
__device__ float g_invD[NN];
__device__ int   g_colcnt[NN];
__device__ int   g_colrows[NN * NN];   // per-column row lists (i-ordered)
__device__ float g_A   [NB * NN * NPD];
__device__ float g_Base[NB * NN * NPD];
__device__ float g_x1  [NB * NN * NU];

// ---------------- kernel 1: mask + row degree + invD ----------------
__global__ void maskdeg_kernel(const float* __restrict__ rel) {
    int i = blockIdx.x;
    int tid = threadIdx.x;
    int cnt = 0;
    for (int j = tid; j < NN; j += 256) {
        const float4* p = reinterpret_cast<const float4*>(rel + ((size_t)i * NN + j) * NK);
        float4 a = p[0], b = p[1];
        float s = a.x + a.y + a.z + a.w + b.x + b.y + b.z + b.w;
        unsigned char m = (s > 0.0f) ? 1 : 0;
        g_mask[i * NN + j] = m;
        cnt += m;
    }
    #pragma unroll
    for (int o = 16; o > 0; o >>= 1) cnt += __shfl_xor_sync(~0u, cnt, o);
    __shared__ int wsum[8];
    if ((tid & 31) == 0) wsum[tid >> 5] = cnt;
    __syncthreads();
    if (tid == 0) {
        int t = 0;
        #pragma unroll
        for (int w = 0; w < 8; w++) t += wsum[w];
        g_invD[i] = 1.0f / (float)(t > 0 ? t : 1);
    }
}

// ---------------- kernel 2: per-column lists + counts (ballot compaction) ----------------
__global__ void colbuild_kernel() {
    int j = blockIdx.x;
    int tid = threadIdx.x;          // row i
    int warp = tid >> 5, lane = tid & 31;
    int flag = g_mask[tid * NN + j];
    unsigned bal = __ballot_sync(~0u, flag != 0);
    __shared__ int wcnt[24];
    __shared__ int wpre[25];
    if (lane == 0) wcnt[warp] = __popc(bal);
    __syncthreads();
    if (tid == 0) {
        int acc = 0;
        #pragma unroll
        for (int w = 0; w < 24; w++) { wpre[w] = acc; acc += wcnt[w]; }
        wpre[24] = acc;
        g_colcnt[j] = acc;
    }
    __syncthreads();
    if (flag) {
        int pos = wpre[warp] + __popc(bal & ((1u << lane) - 1u));
        g_colrows[j * NN + pos] = tid;
    }
}

// ---------------- precompute GEMM (R7 shape, deeper unroll) ----------------
__global__ void __launch_bounds__(PTHREADS) precompute_kernel(
    const float* __restrict__ xext, int use_g,
    const float* __restrict__ W1,
    const float* __restrict__ b1) {
    const float* xp = use_g ? g_x1 : xext;
    __shared__ float sx[RPB][NU];
    __shared__ float spA[RPB][NPD];
    __shared__ float spB[RPB][NPD];
    int R0 = blockIdx.x * RPB;
    int tid = threadIdx.x;
    for (int idx = tid; idx < RPB * NU; idx += PTHREADS)
        sx[idx >> 6][idx & 63] = xp[(size_t)R0 * NU + idx];
    __syncthreads();

    int n  = tid % NPD;
    int kh = tid / NPD;
    float a[RPB], bs[RPB];
    #pragma unroll
    for (int r = 0; r < RPB; r++) { a[r] = 0.0f; bs[r] = 0.0f; }
    if (n < NIN) {
        int ub = kh * 32;
        #pragma unroll 8
        for (int u0 = 0; u0 < 32; u0++) {
            int u = ub + u0;
            float wa = W1[u * NIN + n];
            float wb = W1[(NU + u) * NIN + n];
            #pragma unroll
            for (int r = 0; r < RPB; r++) {
                a[r]  = fmaf(sx[r][u], wa, a[r]);
                bs[r] = fmaf(sx[r][u], wb, bs[r]);
            }
        }
    }
    if (kh == 1) {
        #pragma unroll
        for (int r = 0; r < RPB; r++) { spA[r][n] = a[r]; spB[r][n] = bs[r]; }
    }
    __syncthreads();
    if (kh == 0) {
        float bb = (n < NIN) ? b1[n] : 0.0f;
        #pragma unroll
        for (int r = 0; r < RPB; r++) {
            g_A   [(size_t)(R0 + r) * NPD + n] = a[r] + spA[r][n];
            g_Base[(size_t)(R0 + r) * NPD + n] = bs[r] + spB[r][n] + bb;
        }
    }
}

// ---------------- kernel 4: edge phase ----------------
// Block = 1 column x 4 subset warps (128 threads). Warp sub processes 2 edges x
// 2 batches per iteration; rel-term computed once per edge, shared by batches.
__global__ void __launch_bounds__(128, 6) edge_kernel(
    const float* __restrict__ xin_ext, float* __restrict__ xout_ext,
    int use_g_in, int use_g_out,
    const float* __restrict__ rel,
    const float* __restrict__ W1,      // rows 128..135 = rel weights
    const float* __restrict__ w2,
    const float* __restrict__ b2p)
{
    const float* xin  = use_g_in  ? g_x1 : xin_ext;
    float*       xout = use_g_out ? g_x1 : xout_ext;

    __shared__ float sW1c[NK * NPD];
    __shared__ float sacc[4][2];       // [sub][batch]

    int tid = threadIdx.x, warp = tid >> 5, lane = tid & 31;

    for (int idx = tid; idx < NK * NPD; idx += 128) {
        int kk = idx / NPD, n = idx % NPD;
        sW1c[idx] = (n < NIN) ? W1[(2 * NU + kk) * NIN + n] : 0.0f;
    }
    float w2l[5];
    #pragma unroll
    for (int m = 0; m < 5; m++) {
        int n = lane + 32 * m;
        w2l[m] = (n < NIN) ? w2[n] : 0.0f;
    }
    float b2 = __ldg(b2p);
    __syncthreads();

    int sub = warp;                    // 0..3
    int j   = blockIdx.x;
    int cnt = g_colcnt[j];
    const int* rows = g_colrows + j * NN;

    // hoist Base for (b=0,j) and (b=1,j)
    float base[2][5];
    #pragma unroll
    for (int b = 0; b < 2; b++) {
        const float* Bs = g_Base + ((size_t)(b * NN + j)) * NPD;
        #pragma unroll
        for (int m = 0; m < 5; m++) base[b][m] = Bs[lane + 32 * m];
    }

    float wacc[2] = {0.0f, 0.0f};
    for (int g = sub; 2 * g < cnt; g += 4) {
        int e0 = 2 * g;
        float vdv[2];
        float rv[2][8];
        float av[4][5];     // A loads, chain c = s*2 + b
        int iv[2];

        // front-batched loads: 2x rel LDG.128 + 2x invD + 20x A LDG.32
        #pragma unroll
        for (int s = 0; s < 2; s++) {
            int e = e0 + s;
            bool v = (e < cnt);
            int i = rows[v ? e : 0];
            iv[s] = i;
            vdv[s] = v ? g_invD[i] : 0.0f;
            const float4* rp = reinterpret_cast<const float4*>(
                rel + ((size_t)i * NN + j) * NK);
            float4 r0 = rp[0], r1 = rp[1];
            rv[s][0] = r0.x; rv[s][1] = r0.y; rv[s][2] = r0.z; rv[s][3] = r0.w;
            rv[s][4] = r1.x; rv[s][5] = r1.y; rv[s][6] = r1.z; rv[s][7] = r1.w;
        }
        #pragma unroll
        for (int s = 0; s < 2; s++)
            #pragma unroll
            for (int b = 0; b < 2; b++) {
                const float* Ar = g_A + ((size_t)(b * NN + iv[s])) * NPD;
                #pragma unroll
                for (int m = 0; m < 5; m++)
                    av[s * 2 + b][m] = Ar[lane + 32 * m];
            }

        // rel-term once per EDGE (batch-independent)
        float relc[2][5];
        #pragma unroll
        for (int s = 0; s < 2; s++)
            #pragma unroll
            for (int m = 0; m < 5; m++) relc[s][m] = 0.0f;
        #pragma unroll
        for (int kk = 0; kk < NK; kk++) {
            float w1v[5];
            #pragma unroll
            for (int m = 0; m < 5; m++)
                w1v[m] = sW1c[kk * NPD + lane + 32 * m];
            #pragma unroll
            for (int s = 0; s < 2; s++)
                #pragma unroll
                for (int m = 0; m < 5; m++)
                    relc[s][m] = fmaf(rv[s][kk], w1v[m], relc[s][m]);
        }

        float d[4];
        #pragma unroll
        for (int c = 0; c < 4; c++) {
            int s = c >> 1, b = c & 1;
            float acc = 0.0f;
            #pragma unroll
            for (int m = 0; m < 5; m++) {
                float hv = av[c][m] + (base[b][m] + relc[s][m]);
                hv = fmaxf(hv, SLOPE * hv);
                acc = fmaf(hv, w2l[m], acc);
            }
            d[c] = acc;
        }
        #pragma unroll
        for (int o = 16; o > 0; o >>= 1) {
            #pragma unroll
            for (int c = 0; c < 4; c++)
                d[c] += __shfl_xor_sync(~0u, d[c], o);
        }
        #pragma unroll
        for (int c = 0; c < 4; c++) {
            int s = c >> 1, b = c & 1;
            float o2 = d[c] + b2;
            o2 = fmaxf(o2, SLOPE * o2);
            wacc[b] = fmaf(o2, vdv[s], wacc[b]);
        }
    }

    if (lane == 0) {
        sacc[sub][0] = wacc[0];
        sacc[sub][1] = wacc[1];
    }
    __syncthreads();

    // warps 0..1 write outputs: warp w -> batch b = w
    if (warp < 2) {
        int b = warp;
        float S = ((sacc[0][b] + sacc[1][b]) + sacc[2][b]) + sacc[3][b];
        size_t obase = ((size_t)(b * NN + j)) * NU;
        xout[obase + lane]      = xin[obase + lane]      * S;
        xout[obase + 32 + lane] = xin[obase + 32 + lane] * S;
    }
}

// ---------------- launch ----------------
extern "C" void kernel_launch(void* const* d_in, const int* in_sizes, int n_in,
                              void* d_out, int out_size) {
    const float* seq  = (const float*)d_in[0];
    const float* rel  = (const float*)d_in[1];
    const float* w1_1 = (const float*)d_in[2];
    const float* b1_1 = (const float*)d_in[3];
    const float* w1_2 = (const float*)d_in[4];
    const float* b1_2 = (const float*)d_in[5];
    const float* w2_1 = (const float*)d_in[6];
    const float* b2_1 = (const float*)d_in[7];
    const float* w2_2 = (const float*)d_in[8];
    const float* b2_2 = (const float*)d_in[9];
    float* out = (float*)d_out;

    maskdeg_kernel <<<NN, 256>>>(rel);
    colbuild_kernel<<<NN, 768>>>();

    const int PGRID = NB * NN / RPB;   // 384
    const int EGRID = NN;              // 768 (1 column per block)

    // hop 1: seq -> g_x1 (edge kernel writes x1 directly)
    precompute_kernel<<<PGRID, PTHREADS>>>(seq, 0, w1_1, b1_1);
    edge_kernel      <<<EGRID, 128>>>(seq, nullptr, 0, 1, rel, w1_1, w1_2, b1_2);

    // hop 2: g_x1 -> out
    precompute_kernel<<<PGRID, PTHREADS>>>(nullptr, 1, w2_1, b2_1);
    edge_kernel      <<<EGRID, 128>>>(nullptr, out, 1, 0, rel, w2_1, w2_2, b2_2);
}